// round 7
// baseline (speedup 1.0000x reference)
#include <cuda_runtime.h>
#include <cuda_fp16.h>
#include <math.h>
#include <cstdint>

#define N_TOK 2048
#define HDIM 1024
#define FDIM 4096
#define NEXP 8
#define KSEL 2
#define NPAIR (N_TOK*KSEL)
#define MAXTILES 40
#define BK 32

// ---------------- scratch (static device globals) ----------------
__device__ float  g_logits[N_TOK*NEXP];
__device__ float  g_soft[N_TOK*NEXP];
__device__ float  g_wn[NPAIR];
__device__ int    g_slot[NPAIR];
__device__ int    g_pairtok[NPAIR];
__device__ int    g_tiles[MAXTILES*3];
__device__ int    g_ntiles;
__device__ __half g_xh[(size_t)N_TOK*HDIM];         // x as fp16 (written by gate kernel)
__device__ __half g_Hh[(size_t)(NPAIR+128)*FDIM];   // gelu(x@W1+b1) as fp16
__device__ float  g_Y[(size_t)(NPAIR+128)*HDIM];

// ---------------- helpers ----------------
__device__ __forceinline__ uint32_t pack_h2(float lo, float hi){
    uint32_t r;
    asm("cvt.rn.f16x2.f32 %0, %1, %2;" : "=r"(r) : "f"(hi), "f"(lo));
    return r;
}

__device__ __forceinline__ uint32_t smem_u32(const void* p){
    uint32_t a;
    asm("{ .reg .u64 t; cvta.to.shared.u64 t, %1; cvt.u32.u64 %0, t; }" : "=r"(a) : "l"(p));
    return a;
}

__device__ __forceinline__ void ldsm_x4(uint32_t& r0, uint32_t& r1, uint32_t& r2, uint32_t& r3,
                                        uint32_t addr){
    asm volatile("ldmatrix.sync.aligned.m8n8.x4.shared.b16 {%0,%1,%2,%3}, [%4];"
        : "=r"(r0), "=r"(r1), "=r"(r2), "=r"(r3) : "r"(addr));
}
__device__ __forceinline__ void ldsm_x4_t(uint32_t& r0, uint32_t& r1, uint32_t& r2, uint32_t& r3,
                                          uint32_t addr){
    asm volatile("ldmatrix.sync.aligned.m8n8.x4.trans.shared.b16 {%0,%1,%2,%3}, [%4];"
        : "=r"(r0), "=r"(r1), "=r"(r2), "=r"(r3) : "r"(addr));
}

__device__ __forceinline__ void mma_fp16(float c[4], uint32_t a0, uint32_t a1, uint32_t a2, uint32_t a3,
                                         uint32_t b0, uint32_t b1){
    asm volatile("mma.sync.aligned.m16n8k16.row.col.f32.f16.f16.f32 "
        "{%0,%1,%2,%3}, {%4,%5,%6,%7}, {%8,%9}, {%0,%1,%2,%3};\n"
        : "+f"(c[0]),"+f"(c[1]),"+f"(c[2]),"+f"(c[3])
        : "r"(a0),"r"(a1),"r"(a2),"r"(a3),"r"(b0),"r"(b1));
}

__device__ __forceinline__ float gelu_t(float v){
    float u = 0.7978845608028654f*(v + 0.044715f*v*v*v);
    return 0.5f*v*(1.f + tanhf(u));
}

// ---------------- 1) gating logits + x -> fp16 ----------------
__global__ void gate_kernel(const float* __restrict__ x, const float* __restrict__ Wg,
                            float* __restrict__ logits, __half* __restrict__ xh){
    int i = blockIdx.x;
    int wid = threadIdx.x >> 5;
    int lane = threadIdx.x & 31;
    const float4* x4 = reinterpret_cast<const float4*>(x + (size_t)i*HDIM);
    const float4* w4 = reinterpret_cast<const float4*>(Wg + (size_t)wid*HDIM);
    float s = 0.f;
    #pragma unroll
    for (int k = lane; k < HDIM/4; k += 32){
        float4 a = x4[k], b = w4[k];
        s += a.x*b.x + a.y*b.y + a.z*b.z + a.w*b.w;
        if (wid == 0){
            uint2 h; h.x = pack_h2(a.x, a.y); h.y = pack_h2(a.z, a.w);
            *reinterpret_cast<uint2*>(xh + (size_t)i*HDIM + k*4) = h;
        }
    }
    #pragma unroll
    for (int o = 16; o; o >>= 1) s += __shfl_xor_sync(0xffffffffu, s, o);
    if (lane == 0) logits[i*NEXP + wid] = s;
}

// ---------------- 2) softmax over axis=0 ----------------
__global__ void colsoftmax_kernel(const float* __restrict__ logits, float* __restrict__ soft){
    int e = blockIdx.x;
    int t = threadIdx.x;
    __shared__ float red[256];
    float m = -1e30f;
    for (int i = t; i < N_TOK; i += 256) m = fmaxf(m, logits[i*NEXP + e]);
    red[t] = m; __syncthreads();
    for (int o = 128; o; o >>= 1){ if (t < o) red[t] = fmaxf(red[t], red[t+o]); __syncthreads(); }
    float mx = red[0]; __syncthreads();
    float sum = 0.f;
    for (int i = t; i < N_TOK; i += 256) sum += expf(logits[i*NEXP + e] - mx);
    red[t] = sum; __syncthreads();
    for (int o = 128; o; o >>= 1){ if (t < o) red[t] += red[t+o]; __syncthreads(); }
    float inv = 1.f / red[0];
    for (int i = t; i < N_TOK; i += 256)
        soft[i*NEXP + e] = expf(logits[i*NEXP + e] - mx) * inv;
}

// ---------------- 3) deterministic assignment ----------------
__global__ void assign_kernel(const int* __restrict__ mapping, const float* __restrict__ soft){
    const int T = 512, PPT = NPAIR / T;
    int t = threadIdx.x;
    __shared__ int scan[T][NEXP];
    __shared__ int base[NEXP];

    int cnt[NEXP];
    #pragma unroll
    for (int e = 0; e < NEXP; e++) cnt[e] = 0;
    int le[PPT], lr[PPT];
    #pragma unroll
    for (int j = 0; j < PPT; j++){
        int p = t*PPT + j;
        int e = mapping[p];
        le[j] = e; lr[j] = cnt[e]; cnt[e]++;
    }
    #pragma unroll
    for (int e = 0; e < NEXP; e++) scan[t][e] = cnt[e];
    __syncthreads();
    for (int off = 1; off < T; off <<= 1){
        int v[NEXP];
        if (t >= off){
            #pragma unroll
            for (int e = 0; e < NEXP; e++) v[e] = scan[t-off][e];
        }
        __syncthreads();
        if (t >= off){
            #pragma unroll
            for (int e = 0; e < NEXP; e++) scan[t][e] += v[e];
        }
        __syncthreads();
    }
    if (t == 0){
        int acc = 0;
        for (int e = 0; e < NEXP; e++){ base[e] = acc; acc += scan[T-1][e]; }
        int nt = 0;
        for (int e = 0; e < NEXP; e++){
            int c = scan[T-1][e];
            for (int r = 0; r < c; r += 128){
                g_tiles[nt*3+0] = e;
                g_tiles[nt*3+1] = base[e] + r;
                g_tiles[nt*3+2] = min(128, c - r);
                nt++;
            }
        }
        g_ntiles = nt;
    }
    __syncthreads();
    int excl[NEXP];
    #pragma unroll
    for (int e = 0; e < NEXP; e++) excl[e] = (t > 0 ? scan[t-1][e] : 0);
    #pragma unroll
    for (int j = 0; j < PPT; j++){
        int p = t*PPT + j;
        int e = le[j];
        int dst = base[e] + excl[e] + lr[j];
        g_slot[p] = dst;
        g_pairtok[dst] = p >> 1;
    }
    #pragma unroll
    for (int ii = 0; ii < PPT/KSEL; ii++){
        int i = t*(PPT/KSEL) + ii;
        int e0 = mapping[i*KSEL], e1 = mapping[i*KSEL+1];
        float w0 = soft[i*NEXP + e0], w1 = soft[i*NEXP + e1];
        float inv = 1.f / (w0 + w1);
        g_wn[i*KSEL]   = w0*inv;
        g_wn[i*KSEL+1] = w1*inv;
    }
}

// ---------------- 4) fp16 grouped GEMM: 128x128 tile, BK=32, 4 warps, 64x64 warp tile ----------------
// A smem: [2][128][40] half (M-major, K-contig). B smem: [2][32][136] half (K-major, N-contig).
#define ASTR 40
#define BSTR 136
#define ASZ (128*ASTR)
#define BSZ (BK*BSTR)

template<int KSIZE, int LDB, bool GELU, bool GATHER>
__global__ __launch_bounds__(128, 2) void moe_gemm_fp16(
    const __half* __restrict__ Asrc,  // g_xh (GATHER) or g_Hh
    const float* __restrict__ Ball,   // W [E][KSIZE][LDB] fp32
    const float* __restrict__ bias,   // [E][LDB]
    void* __restrict__ Cbuf,          // half (GELU) or float
    const int* __restrict__ pairtok)
{
    int tileIdx = blockIdx.x;
    if (tileIdx >= g_ntiles) return;
    int e    = g_tiles[tileIdx*3+0];
    int row0 = g_tiles[tileIdx*3+1];
    int rows = g_tiles[tileIdx*3+2];
    int n0   = blockIdx.y * 128;

    extern __shared__ __half smem[];
    __half* As = smem;               // [2][128][ASTR]
    __half* Bs = smem + 2*ASZ;       // [2][BK][BSTR]

    int tid = threadIdx.x;
    int wid = tid >> 5, lane = tid & 31;
    int wm = (wid >> 1) * 64, wn = (wid & 1) * 64;

    // ---- A staging: one full row (32 halves = 4x uint4) per thread ----
    const __half* aH;
    if (GATHER){
        int rr = row0 + ((tid < rows) ? tid : (rows - 1));
        aH = Asrc + (size_t)pairtok[rr] * KSIZE;
    } else {
        aH = Asrc + (size_t)(row0 + tid) * KSIZE;
    }
    // ---- B staging: k-row tid>>2 (32 rows), n-offset (tid&3)*32 (32 floats contiguous) ----
    int bk = tid >> 2;
    int bnq = (tid & 3) * 32;
    const float* bp0 = Ball + (size_t)e * KSIZE * LDB + (size_t)bk * LDB + n0 + bnq;

    float c[4][8][4];
    #pragma unroll
    for (int i = 0; i < 4; i++)
        #pragma unroll
        for (int j = 0; j < 8; j++)
            #pragma unroll
            for (int q = 0; q < 4; q++) c[i][j][q] = 0.f;

    uint4 apre[4];
    uint32_t bpre[16];

    auto prefetch = [&](int kb){
        const uint4* ap = reinterpret_cast<const uint4*>(aH + kb*BK);
        apre[0] = ap[0]; apre[1] = ap[1]; apre[2] = ap[2]; apre[3] = ap[3];
        const float* bp = bp0 + (size_t)kb*BK*LDB;
        #pragma unroll
        for (int j = 0; j < 8; j++){
            float4 v = *reinterpret_cast<const float4*>(bp + j*4);
            bpre[2*j]   = pack_h2(v.x, v.y);
            bpre[2*j+1] = pack_h2(v.z, v.w);
        }
    };

    auto sts = [&](int buf){
        uint4* da = reinterpret_cast<uint4*>(As + buf*ASZ + tid*ASTR);
        da[0] = apre[0]; da[1] = apre[1]; da[2] = apre[2]; da[3] = apre[3];
        uint32_t* db = reinterpret_cast<uint32_t*>(Bs + buf*BSZ + bk*BSTR + bnq);
        #pragma unroll
        for (int j = 0; j < 4; j++)
            *reinterpret_cast<uint4*>(db + 4*j) =
                make_uint4(bpre[4*j], bpre[4*j+1], bpre[4*j+2], bpre[4*j+3]);
    };

    prefetch(0);
    sts(0);
    __syncthreads();

    // ---- per-lane ldmatrix address offsets (in halves) ----
    int a_row = ((lane>>3)&1)*8 + (lane&7);
    int a_kof = ((lane>>4)&1)*8;
    int b_kr  = ((lane>>3)&1)*8 + (lane&7);
    int b_nof = ((lane>>4)&1)*8;

    uint32_t sbA = smem_u32(As);
    uint32_t sbB = smem_u32(Bs);
    uint32_t aoff = (uint32_t)((wm + a_row)*ASTR + a_kof) * 2u;
    uint32_t boff = (uint32_t)(b_kr*BSTR + wn + b_nof) * 2u;

    const int NKB = KSIZE / BK;
    for (int kb = 0; kb < NKB; kb++){
        int cur = kb & 1;
        if (kb + 1 < NKB) prefetch(kb + 1);

        uint32_t abase = sbA + (uint32_t)cur*(ASZ*2) + aoff;
        uint32_t bbase = sbB + (uint32_t)cur*(BSZ*2) + boff;
        #pragma unroll
        for (int ks = 0; ks < 2; ks++){
            uint32_t afr[4][4], bfr[8][2];
            #pragma unroll
            for (int fm = 0; fm < 4; fm++)
                ldsm_x4(afr[fm][0], afr[fm][1], afr[fm][2], afr[fm][3],
                        abase + (uint32_t)(fm*16*ASTR*2) + (uint32_t)(ks*32));
            #pragma unroll
            for (int fn2 = 0; fn2 < 4; fn2++)
                ldsm_x4_t(bfr[2*fn2][0], bfr[2*fn2][1], bfr[2*fn2+1][0], bfr[2*fn2+1][1],
                          bbase + (uint32_t)(ks*16*BSTR*2) + (uint32_t)(fn2*32));
            #pragma unroll
            for (int fm = 0; fm < 4; fm++)
                #pragma unroll
                for (int fn = 0; fn < 8; fn++)
                    mma_fp16(c[fm][fn], afr[fm][0], afr[fm][1], afr[fm][2], afr[fm][3],
                             bfr[fn][0], bfr[fn][1]);
        }
        if (kb + 1 < NKB) sts(cur ^ 1);
        __syncthreads();
    }

    // ---- epilogue ----
    int r_lane = lane >> 2, c_lane = (lane & 3) * 2;
    #pragma unroll
    for (int fm = 0; fm < 4; fm++){
        #pragma unroll
        for (int half_i = 0; half_i < 2; half_i++){
            int mloc = wm + fm*16 + half_i*8 + r_lane;
            if (mloc < rows){
                const float* brw = bias + (size_t)e*LDB + n0;
                #pragma unroll
                for (int fn = 0; fn < 8; fn++){
                    int col = wn + fn*8 + c_lane;
                    float v0 = c[fm][fn][half_i*2+0] + brw[col];
                    float v1 = c[fm][fn][half_i*2+1] + brw[col+1];
                    if (GELU){
                        v0 = gelu_t(v0); v1 = gelu_t(v1);
                        __half* outp = (__half*)Cbuf + (size_t)(row0 + mloc)*LDB + n0 + col;
                        *reinterpret_cast<uint32_t*>(outp) = pack_h2(v0, v1);
                    } else {
                        float* outp = (float*)Cbuf + (size_t)(row0 + mloc)*LDB + n0 + col;
                        float2 st; st.x = v0; st.y = v1;
                        *reinterpret_cast<float2*>(outp) = st;
                    }
                }
            }
        }
    }
}

// ---------------- 5) weighted combine ----------------
__global__ void combine_kernel(float* __restrict__ out){
    int i = blockIdx.x, t = threadIdx.x;
    int s0 = g_slot[i*2], s1 = g_slot[i*2+1];
    float w0 = g_wn[i*2], w1 = g_wn[i*2+1];
    const float4* y0 = reinterpret_cast<const float4*>(g_Y + (size_t)s0*HDIM);
    const float4* y1 = reinterpret_cast<const float4*>(g_Y + (size_t)s1*HDIM);
    float4 a = y0[t], b = y1[t];
    float4 r;
    r.x = w0*a.x + w1*b.x; r.y = w0*a.y + w1*b.y;
    r.z = w0*a.z + w1*b.z; r.w = w0*a.w + w1*b.w;
    reinterpret_cast<float4*>(out + (size_t)i*HDIM)[t] = r;
}

// ---------------- launch ----------------
extern "C" void kernel_launch(void* const* d_in, const int* in_sizes, int n_in,
                              void* d_out, int out_size){
    const float* x       = (const float*)d_in[0];
    const int*   mapping = (const int*)  d_in[1];
    const float* Wg      = (const float*)d_in[2];
    const float* W1      = (const float*)d_in[3];
    const float* b1      = (const float*)d_in[4];
    const float* W2      = (const float*)d_in[5];
    const float* b2      = (const float*)d_in[6];
    float* out = (float*)d_out;

    float *pLog, *pSoft, *pY; __half *pXh, *pHh; int *pTok;
    cudaGetSymbolAddress((void**)&pLog,  g_logits);
    cudaGetSymbolAddress((void**)&pSoft, g_soft);
    cudaGetSymbolAddress((void**)&pXh,   g_xh);
    cudaGetSymbolAddress((void**)&pHh,   g_Hh);
    cudaGetSymbolAddress((void**)&pY,    g_Y);
    cudaGetSymbolAddress((void**)&pTok,  g_pairtok);

    gate_kernel<<<N_TOK, 256>>>(x, Wg, pLog, pXh);
    colsoftmax_kernel<<<NEXP, 256>>>(pLog, pSoft);
    assign_kernel<<<1, 512>>>(mapping, pSoft);

    int smem = (2*ASZ + 2*BSZ) * (int)sizeof(__half);   // 37888 B
    moe_gemm_fp16<HDIM, FDIM, true,  true ><<<dim3(MAXTILES, FDIM/128), 128, smem>>>(pXh, W1, b1, pHh, pTok);
    moe_gemm_fp16<FDIM, HDIM, false, false><<<dim3(MAXTILES, HDIM/128), 128, smem>>>(pHh, W2, b2, pY,  pTok);

    combine_kernel<<<N_TOK, 256>>>(out);
}

// round 8
// speedup vs baseline: 1.4613x; 1.4613x over previous
#include <cuda_runtime.h>
#include <cuda_fp16.h>
#include <math.h>
#include <cstdint>

#define N_TOK 2048
#define HDIM 1024
#define FDIM 4096
#define NEXP 8
#define KSEL 2
#define NPAIR (N_TOK*KSEL)
#define MAXTILES 40
#define BK 32

// ---------------- scratch (static device globals) ----------------
__device__ float  g_logits[N_TOK*NEXP];
__device__ float  g_soft[N_TOK*NEXP];
__device__ float  g_wn[NPAIR];
__device__ int    g_slot[NPAIR];
__device__ int    g_pairtok[NPAIR];
__device__ int    g_tiles[MAXTILES*3];
__device__ int    g_ntiles;
__device__ __half g_xh[(size_t)N_TOK*HDIM];         // x as fp16 (written by gate kernel)
__device__ __half g_Hh[(size_t)(NPAIR+128)*FDIM];   // gelu(x@W1+b1) as fp16
__device__ float  g_Y[(size_t)(NPAIR+128)*HDIM];

// ---------------- helpers ----------------
__device__ __forceinline__ uint32_t pack_h2(float lo, float hi){
    uint32_t r;
    asm("cvt.rn.f16x2.f32 %0, %1, %2;" : "=r"(r) : "f"(hi), "f"(lo));
    return r;
}

__device__ __forceinline__ uint32_t smem_u32(const void* p){
    uint32_t a;
    asm("{ .reg .u64 t; cvta.to.shared.u64 t, %1; cvt.u32.u64 %0, t; }" : "=r"(a) : "l"(p));
    return a;
}

#define CP_ASYNC16(dst, src) \
    asm volatile("cp.async.cg.shared.global [%0], [%1], 16;" :: "r"(dst), "l"(src) : "memory")
#define CP_COMMIT() asm volatile("cp.async.commit_group;" ::: "memory")
#define CP_WAIT0()  asm volatile("cp.async.wait_group 0;" ::: "memory")

__device__ __forceinline__ void ldsm_x4(uint32_t& r0, uint32_t& r1, uint32_t& r2, uint32_t& r3,
                                        uint32_t addr){
    asm volatile("ldmatrix.sync.aligned.m8n8.x4.shared.b16 {%0,%1,%2,%3}, [%4];"
        : "=r"(r0), "=r"(r1), "=r"(r2), "=r"(r3) : "r"(addr));
}
__device__ __forceinline__ void ldsm_x4_t(uint32_t& r0, uint32_t& r1, uint32_t& r2, uint32_t& r3,
                                          uint32_t addr){
    asm volatile("ldmatrix.sync.aligned.m8n8.x4.trans.shared.b16 {%0,%1,%2,%3}, [%4];"
        : "=r"(r0), "=r"(r1), "=r"(r2), "=r"(r3) : "r"(addr));
}

__device__ __forceinline__ void mma_fp16(float c[4], uint32_t a0, uint32_t a1, uint32_t a2, uint32_t a3,
                                         uint32_t b0, uint32_t b1){
    asm volatile("mma.sync.aligned.m16n8k16.row.col.f32.f16.f16.f32 "
        "{%0,%1,%2,%3}, {%4,%5,%6,%7}, {%8,%9}, {%0,%1,%2,%3};\n"
        : "+f"(c[0]),"+f"(c[1]),"+f"(c[2]),"+f"(c[3])
        : "r"(a0),"r"(a1),"r"(a2),"r"(a3),"r"(b0),"r"(b1));
}

__device__ __forceinline__ float gelu_t(float v){
    float u = 0.7978845608028654f*(v + 0.044715f*v*v*v);
    return 0.5f*v*(1.f + tanhf(u));
}

// ---------------- 1) gating logits + x -> fp16 ----------------
__global__ void gate_kernel(const float* __restrict__ x, const float* __restrict__ Wg,
                            float* __restrict__ logits, __half* __restrict__ xh){
    int i = blockIdx.x;
    int wid = threadIdx.x >> 5;
    int lane = threadIdx.x & 31;
    const float4* x4 = reinterpret_cast<const float4*>(x + (size_t)i*HDIM);
    const float4* w4 = reinterpret_cast<const float4*>(Wg + (size_t)wid*HDIM);
    float s = 0.f;
    #pragma unroll
    for (int k = lane; k < HDIM/4; k += 32){
        float4 a = x4[k], b = w4[k];
        s += a.x*b.x + a.y*b.y + a.z*b.z + a.w*b.w;
        if (wid == 0){
            uint2 h; h.x = pack_h2(a.x, a.y); h.y = pack_h2(a.z, a.w);
            *reinterpret_cast<uint2*>(xh + (size_t)i*HDIM + k*4) = h;
        }
    }
    #pragma unroll
    for (int o = 16; o; o >>= 1) s += __shfl_xor_sync(0xffffffffu, s, o);
    if (lane == 0) logits[i*NEXP + wid] = s;
}

// ---------------- 2) softmax over axis=0 ----------------
__global__ void colsoftmax_kernel(const float* __restrict__ logits, float* __restrict__ soft){
    int e = blockIdx.x;
    int t = threadIdx.x;
    __shared__ float red[256];
    float m = -1e30f;
    for (int i = t; i < N_TOK; i += 256) m = fmaxf(m, logits[i*NEXP + e]);
    red[t] = m; __syncthreads();
    for (int o = 128; o; o >>= 1){ if (t < o) red[t] = fmaxf(red[t], red[t+o]); __syncthreads(); }
    float mx = red[0]; __syncthreads();
    float sum = 0.f;
    for (int i = t; i < N_TOK; i += 256) sum += expf(logits[i*NEXP + e] - mx);
    red[t] = sum; __syncthreads();
    for (int o = 128; o; o >>= 1){ if (t < o) red[t] += red[t+o]; __syncthreads(); }
    float inv = 1.f / red[0];
    for (int i = t; i < N_TOK; i += 256)
        soft[i*NEXP + e] = expf(logits[i*NEXP + e] - mx) * inv;
}

// ---------------- 3) deterministic assignment ----------------
__global__ void assign_kernel(const int* __restrict__ mapping, const float* __restrict__ soft){
    const int T = 512, PPT = NPAIR / T;
    int t = threadIdx.x;
    __shared__ int scan[T][NEXP];
    __shared__ int base[NEXP];

    int cnt[NEXP];
    #pragma unroll
    for (int e = 0; e < NEXP; e++) cnt[e] = 0;
    int le[PPT], lr[PPT];
    #pragma unroll
    for (int j = 0; j < PPT; j++){
        int p = t*PPT + j;
        int e = mapping[p];
        le[j] = e; lr[j] = cnt[e]; cnt[e]++;
    }
    #pragma unroll
    for (int e = 0; e < NEXP; e++) scan[t][e] = cnt[e];
    __syncthreads();
    for (int off = 1; off < T; off <<= 1){
        int v[NEXP];
        if (t >= off){
            #pragma unroll
            for (int e = 0; e < NEXP; e++) v[e] = scan[t-off][e];
        }
        __syncthreads();
        if (t >= off){
            #pragma unroll
            for (int e = 0; e < NEXP; e++) scan[t][e] += v[e];
        }
        __syncthreads();
    }
    if (t == 0){
        int acc = 0;
        for (int e = 0; e < NEXP; e++){ base[e] = acc; acc += scan[T-1][e]; }
        int nt = 0;
        for (int e = 0; e < NEXP; e++){
            int c = scan[T-1][e];
            for (int r = 0; r < c; r += 128){
                g_tiles[nt*3+0] = e;
                g_tiles[nt*3+1] = base[e] + r;
                g_tiles[nt*3+2] = min(128, c - r);
                nt++;
            }
        }
        g_ntiles = nt;
    }
    __syncthreads();
    int excl[NEXP];
    #pragma unroll
    for (int e = 0; e < NEXP; e++) excl[e] = (t > 0 ? scan[t-1][e] : 0);
    #pragma unroll
    for (int j = 0; j < PPT; j++){
        int p = t*PPT + j;
        int e = le[j];
        int dst = base[e] + excl[e] + lr[j];
        g_slot[p] = dst;
        g_pairtok[dst] = p >> 1;
    }
    #pragma unroll
    for (int ii = 0; ii < PPT/KSEL; ii++){
        int i = t*(PPT/KSEL) + ii;
        int e0 = mapping[i*KSEL], e1 = mapping[i*KSEL+1];
        float w0 = soft[i*NEXP + e0], w1 = soft[i*NEXP + e1];
        float inv = 1.f / (w0 + w1);
        g_wn[i*KSEL]   = w0*inv;
        g_wn[i*KSEL+1] = w1*inv;
    }
}

// ---------------- 4) fp16 grouped GEMM: 128x128 tile, BK=32, 8 warps, 64x32 warp tile ----------------
// A smem: [2][128][40] half (M-major, K-contig), filled via cp.async (A is already fp16).
// B smem: [2][32][136] half (K-major, N-contig), fp32 LDG -> cvt -> STS.
#define ASTR 40
#define BSTR 136
#define ASZ (128*ASTR)
#define BSZ (BK*BSTR)

template<int KSIZE, int LDB, bool GELU, bool GATHER>
__global__ __launch_bounds__(256, 2) void moe_gemm_fp16(
    const __half* __restrict__ Asrc,  // g_xh (GATHER) or g_Hh
    const float* __restrict__ Ball,   // W [E][KSIZE][LDB] fp32
    const float* __restrict__ bias,   // [E][LDB]
    void* __restrict__ Cbuf,          // half (GELU) or float
    const int* __restrict__ pairtok)
{
    int tileIdx = blockIdx.x;
    if (tileIdx >= g_ntiles) return;
    int e    = g_tiles[tileIdx*3+0];
    int row0 = g_tiles[tileIdx*3+1];
    int rows = g_tiles[tileIdx*3+2];
    int n0   = blockIdx.y * 128;

    extern __shared__ __half smem[];
    __half* As = smem;               // [2][128][ASTR]
    __half* Bs = smem + 2*ASZ;       // [2][BK][BSTR]

    int tid = threadIdx.x;
    int wid = tid >> 5, lane = tid & 31;
    int wm = (wid >> 2) * 64, wn = (wid & 3) * 32;

    // ---- A staging: 2 threads per row; each copies 16 halves (2x 16B) via cp.async ----
    int arow = tid >> 1;
    int koff = (tid & 1) * 16;      // half offset within row
    const __half* aH;
    if (GATHER){
        int rr = row0 + ((arow < rows) ? arow : (rows - 1));
        aH = Asrc + (size_t)pairtok[rr] * KSIZE + koff;
    } else {
        aH = Asrc + (size_t)(row0 + arow) * KSIZE + koff;
    }
    uint32_t sbA = smem_u32(As);
    uint32_t sbB = smem_u32(Bs);
    uint32_t a_dst0 = sbA + (uint32_t)(arow*ASTR + koff)*2u;

    // ---- B staging: k-row tid>>3 (32 rows), n-offset (tid&7)*16 (16 fp32 -> 16 halves) ----
    int bk = tid >> 3;
    int bnq = (tid & 7) * 16;
    const float* bp0 = Ball + (size_t)e * KSIZE * LDB + (size_t)bk * LDB + n0 + bnq;

    float c[4][4][4];
    #pragma unroll
    for (int i = 0; i < 4; i++)
        #pragma unroll
        for (int j = 0; j < 4; j++)
            #pragma unroll
            for (int q = 0; q < 4; q++) c[i][j][q] = 0.f;

    uint32_t bpre[8];

    auto cp_a = [&](int buf, int kb){
        uint32_t d = a_dst0 + (uint32_t)buf*(ASZ*2);
        const __half* s = aH + kb*BK;
        CP_ASYNC16(d,      s);
        CP_ASYNC16(d + 16, s + 8);
        CP_COMMIT();
    };
    auto ldg_b = [&](int kb){
        const float* bp = bp0 + (size_t)kb*BK*LDB;
        #pragma unroll
        for (int j = 0; j < 4; j++){
            float4 v = *reinterpret_cast<const float4*>(bp + j*4);
            bpre[2*j]   = pack_h2(v.x, v.y);
            bpre[2*j+1] = pack_h2(v.z, v.w);
        }
    };
    auto sts_b = [&](int buf){
        uint32_t* db = reinterpret_cast<uint32_t*>(Bs + buf*BSZ + bk*BSTR + bnq);
        *reinterpret_cast<uint4*>(db)     = make_uint4(bpre[0], bpre[1], bpre[2], bpre[3]);
        *reinterpret_cast<uint4*>(db + 4) = make_uint4(bpre[4], bpre[5], bpre[6], bpre[7]);
    };

    cp_a(0, 0);
    ldg_b(0);
    sts_b(0);
    CP_WAIT0();
    __syncthreads();

    // ---- per-lane ldmatrix address offsets (in halves) ----
    int a_row = ((lane>>3)&1)*8 + (lane&7);
    int a_kof = ((lane>>4)&1)*8;
    int b_kr  = ((lane>>3)&1)*8 + (lane&7);
    int b_nof = ((lane>>4)&1)*8;

    uint32_t aoff = (uint32_t)((wm + a_row)*ASTR + a_kof) * 2u;
    uint32_t boff = (uint32_t)(b_kr*BSTR + wn + b_nof) * 2u;

    const int NKB = KSIZE / BK;
    for (int kb = 0; kb < NKB; kb++){
        int cur = kb & 1;
        if (kb + 1 < NKB){
            cp_a(cur ^ 1, kb + 1);
            ldg_b(kb + 1);
        }

        uint32_t abase = sbA + (uint32_t)cur*(ASZ*2) + aoff;
        uint32_t bbase = sbB + (uint32_t)cur*(BSZ*2) + boff;
        #pragma unroll
        for (int ks = 0; ks < 2; ks++){
            uint32_t afr[4][4], bfr[4][2];
            #pragma unroll
            for (int fm = 0; fm < 4; fm++)
                ldsm_x4(afr[fm][0], afr[fm][1], afr[fm][2], afr[fm][3],
                        abase + (uint32_t)(fm*16*ASTR*2) + (uint32_t)(ks*32));
            #pragma unroll
            for (int fn2 = 0; fn2 < 2; fn2++)
                ldsm_x4_t(bfr[2*fn2][0], bfr[2*fn2][1], bfr[2*fn2+1][0], bfr[2*fn2+1][1],
                          bbase + (uint32_t)(ks*16*BSTR*2) + (uint32_t)(fn2*32));
            #pragma unroll
            for (int fm = 0; fm < 4; fm++)
                #pragma unroll
                for (int fn = 0; fn < 4; fn++)
                    mma_fp16(c[fm][fn], afr[fm][0], afr[fm][1], afr[fm][2], afr[fm][3],
                             bfr[fn][0], bfr[fn][1]);
        }
        if (kb + 1 < NKB){
            sts_b(cur ^ 1);
            CP_WAIT0();
        }
        __syncthreads();
    }

    // ---- epilogue ----
    int r_lane = lane >> 2, c_lane = (lane & 3) * 2;
    #pragma unroll
    for (int fm = 0; fm < 4; fm++){
        #pragma unroll
        for (int half_i = 0; half_i < 2; half_i++){
            int mloc = wm + fm*16 + half_i*8 + r_lane;
            if (mloc < rows){
                const float* brw = bias + (size_t)e*LDB + n0;
                #pragma unroll
                for (int fn = 0; fn < 4; fn++){
                    int col = wn + fn*8 + c_lane;
                    float v0 = c[fm][fn][half_i*2+0] + brw[col];
                    float v1 = c[fm][fn][half_i*2+1] + brw[col+1];
                    if (GELU){
                        v0 = gelu_t(v0); v1 = gelu_t(v1);
                        __half* outp = (__half*)Cbuf + (size_t)(row0 + mloc)*LDB + n0 + col;
                        *reinterpret_cast<uint32_t*>(outp) = pack_h2(v0, v1);
                    } else {
                        float* outp = (float*)Cbuf + (size_t)(row0 + mloc)*LDB + n0 + col;
                        float2 st; st.x = v0; st.y = v1;
                        *reinterpret_cast<float2*>(outp) = st;
                    }
                }
            }
        }
    }
}

// ---------------- 5) weighted combine ----------------
__global__ void combine_kernel(float* __restrict__ out){
    int i = blockIdx.x, t = threadIdx.x;
    int s0 = g_slot[i*2], s1 = g_slot[i*2+1];
    float w0 = g_wn[i*2], w1 = g_wn[i*2+1];
    const float4* y0 = reinterpret_cast<const float4*>(g_Y + (size_t)s0*HDIM);
    const float4* y1 = reinterpret_cast<const float4*>(g_Y + (size_t)s1*HDIM);
    float4 a = y0[t], b = y1[t];
    float4 r;
    r.x = w0*a.x + w1*b.x; r.y = w0*a.y + w1*b.y;
    r.z = w0*a.z + w1*b.z; r.w = w0*a.w + w1*b.w;
    reinterpret_cast<float4*>(out + (size_t)i*HDIM)[t] = r;
}

// ---------------- launch ----------------
extern "C" void kernel_launch(void* const* d_in, const int* in_sizes, int n_in,
                              void* d_out, int out_size){
    const float* x       = (const float*)d_in[0];
    const int*   mapping = (const int*)  d_in[1];
    const float* Wg      = (const float*)d_in[2];
    const float* W1      = (const float*)d_in[3];
    const float* b1      = (const float*)d_in[4];
    const float* W2      = (const float*)d_in[5];
    const float* b2      = (const float*)d_in[6];
    float* out = (float*)d_out;

    float *pLog, *pSoft, *pY; __half *pXh, *pHh; int *pTok;
    cudaGetSymbolAddress((void**)&pLog,  g_logits);
    cudaGetSymbolAddress((void**)&pSoft, g_soft);
    cudaGetSymbolAddress((void**)&pXh,   g_xh);
    cudaGetSymbolAddress((void**)&pHh,   g_Hh);
    cudaGetSymbolAddress((void**)&pY,    g_Y);
    cudaGetSymbolAddress((void**)&pTok,  g_pairtok);

    gate_kernel<<<N_TOK, 256>>>(x, Wg, pLog, pXh);
    colsoftmax_kernel<<<NEXP, 256>>>(pLog, pSoft);
    assign_kernel<<<1, 512>>>(mapping, pSoft);

    int smem = (2*ASZ + 2*BSZ) * (int)sizeof(__half);   // 37888 B
    moe_gemm_fp16<HDIM, FDIM, true,  true ><<<dim3(MAXTILES, FDIM/128), 256, smem>>>(pXh, W1, b1, pHh, pTok);
    moe_gemm_fp16<FDIM, HDIM, false, false><<<dim3(MAXTILES, HDIM/128), 256, smem>>>(pHh, W2, b2, pY,  pTok);

    combine_kernel<<<N_TOK, 256>>>(out);
}

// round 9
// speedup vs baseline: 1.5851x; 1.0847x over previous
#include <cuda_runtime.h>
#include <cuda_fp16.h>
#include <math.h>
#include <cstdint>

#define N_TOK 2048
#define HDIM 1024
#define FDIM 4096
#define NEXP 8
#define KSEL 2
#define NPAIR (N_TOK*KSEL)
#define MAXTILES 40
#define BK 32
#define BN 256

// ---------------- scratch (static device globals) ----------------
__device__ float  g_logits[N_TOK*NEXP];
__device__ float  g_soft[N_TOK*NEXP];
__device__ float  g_wn[NPAIR];
__device__ int    g_slot[NPAIR];
__device__ int    g_pairtok[NPAIR];
__device__ int    g_tiles[MAXTILES*3];
__device__ int    g_ntiles;
__device__ __half g_xh[(size_t)N_TOK*HDIM];           // x as fp16 (written by gate kernel)
__device__ __half g_Hh[(size_t)(NPAIR+128)*FDIM];     // gelu(x@W1+b1) as fp16
__device__ float  g_Y[(size_t)(NPAIR+128)*HDIM];
__device__ __half g_W1h[(size_t)NEXP*HDIM*FDIM];      // W1 as fp16
__device__ __half g_W2h[(size_t)NEXP*FDIM*HDIM];      // W2 as fp16

// ---------------- helpers ----------------
__device__ __forceinline__ uint32_t pack_h2(float lo, float hi){
    uint32_t r;
    asm("cvt.rn.f16x2.f32 %0, %1, %2;" : "=r"(r) : "f"(hi), "f"(lo));
    return r;
}

__device__ __forceinline__ uint32_t smem_u32(const void* p){
    uint32_t a;
    asm("{ .reg .u64 t; cvta.to.shared.u64 t, %1; cvt.u32.u64 %0, t; }" : "=r"(a) : "l"(p));
    return a;
}

#define CP_ASYNC16(dst, src) \
    asm volatile("cp.async.cg.shared.global [%0], [%1], 16;" :: "r"(dst), "l"(src) : "memory")
#define CP_COMMIT() asm volatile("cp.async.commit_group;" ::: "memory")
#define CP_WAIT0()  asm volatile("cp.async.wait_group 0;" ::: "memory")

__device__ __forceinline__ void ldsm_x4(uint32_t& r0, uint32_t& r1, uint32_t& r2, uint32_t& r3,
                                        uint32_t addr){
    asm volatile("ldmatrix.sync.aligned.m8n8.x4.shared.b16 {%0,%1,%2,%3}, [%4];"
        : "=r"(r0), "=r"(r1), "=r"(r2), "=r"(r3) : "r"(addr));
}
__device__ __forceinline__ void ldsm_x4_t(uint32_t& r0, uint32_t& r1, uint32_t& r2, uint32_t& r3,
                                          uint32_t addr){
    asm volatile("ldmatrix.sync.aligned.m8n8.x4.trans.shared.b16 {%0,%1,%2,%3}, [%4];"
        : "=r"(r0), "=r"(r1), "=r"(r2), "=r"(r3) : "r"(addr));
}

__device__ __forceinline__ void mma_fp16(float c[4], uint32_t a0, uint32_t a1, uint32_t a2, uint32_t a3,
                                         uint32_t b0, uint32_t b1){
    asm volatile("mma.sync.aligned.m16n8k16.row.col.f32.f16.f16.f32 "
        "{%0,%1,%2,%3}, {%4,%5,%6,%7}, {%8,%9}, {%0,%1,%2,%3};\n"
        : "+f"(c[0]),"+f"(c[1]),"+f"(c[2]),"+f"(c[3])
        : "r"(a0),"r"(a1),"r"(a2),"r"(a3),"r"(b0),"r"(b1));
}

__device__ __forceinline__ float gelu_t(float v){
    float u = 0.7978845608028654f*(v + 0.044715f*v*v*v);
    return 0.5f*v*(1.f + tanhf(u));
}

// ---------------- 0) weight conversion fp32 -> fp16 ----------------
__global__ void convw_kernel(const float* __restrict__ W1, const float* __restrict__ W2,
                             __half* __restrict__ W1h, __half* __restrict__ W2h){
    size_t n4 = (size_t)NEXP*HDIM*FDIM/4;   // same count for W1 and W2
    size_t stride = (size_t)gridDim.x*blockDim.x;
    for (size_t i = (size_t)blockIdx.x*blockDim.x + threadIdx.x; i < n4; i += stride){
        float4 v = reinterpret_cast<const float4*>(W1)[i];
        uint2 h; h.x = pack_h2(v.x, v.y); h.y = pack_h2(v.z, v.w);
        reinterpret_cast<uint2*>(W1h)[i] = h;
        float4 w = reinterpret_cast<const float4*>(W2)[i];
        uint2 g; g.x = pack_h2(w.x, w.y); g.y = pack_h2(w.z, w.w);
        reinterpret_cast<uint2*>(W2h)[i] = g;
    }
}

// ---------------- 1) gating logits + x -> fp16 ----------------
__global__ void gate_kernel(const float* __restrict__ x, const float* __restrict__ Wg,
                            float* __restrict__ logits, __half* __restrict__ xh){
    int i = blockIdx.x;
    int wid = threadIdx.x >> 5;
    int lane = threadIdx.x & 31;
    const float4* x4 = reinterpret_cast<const float4*>(x + (size_t)i*HDIM);
    const float4* w4 = reinterpret_cast<const float4*>(Wg + (size_t)wid*HDIM);
    float s = 0.f;
    #pragma unroll
    for (int k = lane; k < HDIM/4; k += 32){
        float4 a = x4[k], b = w4[k];
        s += a.x*b.x + a.y*b.y + a.z*b.z + a.w*b.w;
        if (wid == 0){
            uint2 h; h.x = pack_h2(a.x, a.y); h.y = pack_h2(a.z, a.w);
            *reinterpret_cast<uint2*>(xh + (size_t)i*HDIM + k*4) = h;
        }
    }
    #pragma unroll
    for (int o = 16; o; o >>= 1) s += __shfl_xor_sync(0xffffffffu, s, o);
    if (lane == 0) logits[i*NEXP + wid] = s;
}

// ---------------- 2) softmax over axis=0 ----------------
__global__ void colsoftmax_kernel(const float* __restrict__ logits, float* __restrict__ soft){
    int e = blockIdx.x;
    int t = threadIdx.x;
    __shared__ float red[256];
    float m = -1e30f;
    for (int i = t; i < N_TOK; i += 256) m = fmaxf(m, logits[i*NEXP + e]);
    red[t] = m; __syncthreads();
    for (int o = 128; o; o >>= 1){ if (t < o) red[t] = fmaxf(red[t], red[t+o]); __syncthreads(); }
    float mx = red[0]; __syncthreads();
    float sum = 0.f;
    for (int i = t; i < N_TOK; i += 256) sum += expf(logits[i*NEXP + e] - mx);
    red[t] = sum; __syncthreads();
    for (int o = 128; o; o >>= 1){ if (t < o) red[t] += red[t+o]; __syncthreads(); }
    float inv = 1.f / red[0];
    for (int i = t; i < N_TOK; i += 256)
        soft[i*NEXP + e] = expf(logits[i*NEXP + e] - mx) * inv;
}

// ---------------- 3) deterministic assignment ----------------
__global__ void assign_kernel(const int* __restrict__ mapping, const float* __restrict__ soft){
    const int T = 512, PPT = NPAIR / T;
    int t = threadIdx.x;
    __shared__ int scan[T][NEXP];
    __shared__ int base[NEXP];

    int cnt[NEXP];
    #pragma unroll
    for (int e = 0; e < NEXP; e++) cnt[e] = 0;
    int le[PPT], lr[PPT];
    #pragma unroll
    for (int j = 0; j < PPT; j++){
        int p = t*PPT + j;
        int e = mapping[p];
        le[j] = e; lr[j] = cnt[e]; cnt[e]++;
    }
    #pragma unroll
    for (int e = 0; e < NEXP; e++) scan[t][e] = cnt[e];
    __syncthreads();
    for (int off = 1; off < T; off <<= 1){
        int v[NEXP];
        if (t >= off){
            #pragma unroll
            for (int e = 0; e < NEXP; e++) v[e] = scan[t-off][e];
        }
        __syncthreads();
        if (t >= off){
            #pragma unroll
            for (int e = 0; e < NEXP; e++) scan[t][e] += v[e];
        }
        __syncthreads();
    }
    if (t == 0){
        int acc = 0;
        for (int e = 0; e < NEXP; e++){ base[e] = acc; acc += scan[T-1][e]; }
        int nt = 0;
        for (int e = 0; e < NEXP; e++){
            int c = scan[T-1][e];
            for (int r = 0; r < c; r += 128){
                g_tiles[nt*3+0] = e;
                g_tiles[nt*3+1] = base[e] + r;
                g_tiles[nt*3+2] = min(128, c - r);
                nt++;
            }
        }
        g_ntiles = nt;
    }
    __syncthreads();
    int excl[NEXP];
    #pragma unroll
    for (int e = 0; e < NEXP; e++) excl[e] = (t > 0 ? scan[t-1][e] : 0);
    #pragma unroll
    for (int j = 0; j < PPT; j++){
        int p = t*PPT + j;
        int e = le[j];
        int dst = base[e] + excl[e] + lr[j];
        g_slot[p] = dst;
        g_pairtok[dst] = p >> 1;
    }
    #pragma unroll
    for (int ii = 0; ii < PPT/KSEL; ii++){
        int i = t*(PPT/KSEL) + ii;
        int e0 = mapping[i*KSEL], e1 = mapping[i*KSEL+1];
        float w0 = soft[i*NEXP + e0], w1 = soft[i*NEXP + e1];
        float inv = 1.f / (w0 + w1);
        g_wn[i*KSEL]   = w0*inv;
        g_wn[i*KSEL+1] = w1*inv;
    }
}

// ---------------- 4) fp16 grouped GEMM: 128x256 tile, BK=32, 16 warps, 32x64 warp tile ----------------
// A smem: [2][128][40] half, cp.async. B smem: [2][32][264] half (K-major, N-contig), cp.async.
#define ASTR 40
#define BSTR 264
#define ASZ (128*ASTR)
#define BSZ (BK*BSTR)
#define SMEM_BYTES ((2*ASZ + 2*BSZ) * 2)

template<int KSIZE, int LDB, bool GELU, bool GATHER>
__global__ __launch_bounds__(512, 1) void moe_gemm_fp16(
    const __half* __restrict__ Asrc,  // g_xh (GATHER) or g_Hh
    const __half* __restrict__ Ball,  // W fp16 [E][KSIZE][LDB]
    const float* __restrict__ bias,   // [E][LDB]
    void* __restrict__ Cbuf,          // half (GELU) or float
    const int* __restrict__ pairtok)
{
    int tileIdx = blockIdx.x;
    if (tileIdx >= g_ntiles) return;
    int e    = g_tiles[tileIdx*3+0];
    int row0 = g_tiles[tileIdx*3+1];
    int rows = g_tiles[tileIdx*3+2];
    int n0   = blockIdx.y * BN;

    extern __shared__ __half smem[];
    __half* As = smem;               // [2][128][ASTR]
    __half* Bs = smem + 2*ASZ;       // [2][BK][BSTR]

    int tid = threadIdx.x;
    int wid = tid >> 5, lane = tid & 31;
    int wm = (wid >> 2) * 32, wn = (wid & 3) * 64;

    // ---- A staging: 4 threads per row; each one cp.async16 (8 halves) ----
    int arow = tid >> 2;
    int koff = (tid & 3) * 8;
    const __half* aH;
    if (GATHER){
        int rr = row0 + ((arow < rows) ? arow : (rows - 1));
        aH = Asrc + (size_t)pairtok[rr] * KSIZE + koff;
    } else {
        aH = Asrc + (size_t)(row0 + arow) * KSIZE + koff;
    }
    uint32_t sbA = smem_u32(As);
    uint32_t sbB = smem_u32(Bs);
    uint32_t a_dst0 = sbA + (uint32_t)(arow*ASTR + koff)*2u;

    // ---- B staging: 16 threads per k-row; each 2x cp.async16 (16 halves) ----
    int brow = tid >> 4;
    int bcol = (tid & 15) * 16;
    const __half* bp0 = Ball + (size_t)e * KSIZE * LDB + (size_t)brow * LDB + n0 + bcol;
    uint32_t b_dst0 = sbB + (uint32_t)(brow*BSTR + bcol)*2u;

    float c[2][8][4];
    #pragma unroll
    for (int i = 0; i < 2; i++)
        #pragma unroll
        for (int j = 0; j < 8; j++)
            #pragma unroll
            for (int q = 0; q < 4; q++) c[i][j][q] = 0.f;

    auto cp_tiles = [&](int buf, int kb){
        uint32_t da = a_dst0 + (uint32_t)buf*(ASZ*2);
        CP_ASYNC16(da, aH + kb*BK);
        uint32_t db = b_dst0 + (uint32_t)buf*(BSZ*2);
        const __half* bs = bp0 + (size_t)kb*BK*LDB;
        CP_ASYNC16(db,      bs);
        CP_ASYNC16(db + 16, bs + 8);
        CP_COMMIT();
    };

    cp_tiles(0, 0);
    CP_WAIT0();
    __syncthreads();

    // ---- per-lane ldmatrix address offsets ----
    int a_row = ((lane>>3)&1)*8 + (lane&7);
    int a_kof = ((lane>>4)&1)*8;
    int b_kr  = ((lane>>3)&1)*8 + (lane&7);
    int b_nof = ((lane>>4)&1)*8;

    uint32_t aoff = (uint32_t)((wm + a_row)*ASTR + a_kof) * 2u;
    uint32_t boff = (uint32_t)(b_kr*BSTR + wn + b_nof) * 2u;

    const int NKB = KSIZE / BK;
    for (int kb = 0; kb < NKB; kb++){
        int cur = kb & 1;
        if (kb + 1 < NKB) cp_tiles(cur ^ 1, kb + 1);

        uint32_t abase = sbA + (uint32_t)cur*(ASZ*2) + aoff;
        uint32_t bbase = sbB + (uint32_t)cur*(BSZ*2) + boff;
        #pragma unroll
        for (int ks = 0; ks < 2; ks++){
            uint32_t afr[2][4], bfr[8][2];
            #pragma unroll
            for (int fm = 0; fm < 2; fm++)
                ldsm_x4(afr[fm][0], afr[fm][1], afr[fm][2], afr[fm][3],
                        abase + (uint32_t)(fm*16*ASTR*2) + (uint32_t)(ks*32));
            #pragma unroll
            for (int fn2 = 0; fn2 < 4; fn2++)
                ldsm_x4_t(bfr[2*fn2][0], bfr[2*fn2][1], bfr[2*fn2+1][0], bfr[2*fn2+1][1],
                          bbase + (uint32_t)(ks*16*BSTR*2) + (uint32_t)(fn2*32));
            #pragma unroll
            for (int fm = 0; fm < 2; fm++)
                #pragma unroll
                for (int fn = 0; fn < 8; fn++)
                    mma_fp16(c[fm][fn], afr[fm][0], afr[fm][1], afr[fm][2], afr[fm][3],
                             bfr[fn][0], bfr[fn][1]);
        }
        if (kb + 1 < NKB) CP_WAIT0();
        __syncthreads();
    }

    // ---- epilogue ----
    int r_lane = lane >> 2, c_lane = (lane & 3) * 2;
    #pragma unroll
    for (int fm = 0; fm < 2; fm++){
        #pragma unroll
        for (int half_i = 0; half_i < 2; half_i++){
            int mloc = wm + fm*16 + half_i*8 + r_lane;
            if (mloc < rows){
                const float* brw = bias + (size_t)e*LDB + n0;
                #pragma unroll
                for (int fn = 0; fn < 8; fn++){
                    int col = wn + fn*8 + c_lane;
                    float v0 = c[fm][fn][half_i*2+0] + brw[col];
                    float v1 = c[fm][fn][half_i*2+1] + brw[col+1];
                    if (GELU){
                        v0 = gelu_t(v0); v1 = gelu_t(v1);
                        __half* outp = (__half*)Cbuf + (size_t)(row0 + mloc)*LDB + n0 + col;
                        *reinterpret_cast<uint32_t*>(outp) = pack_h2(v0, v1);
                    } else {
                        float* outp = (float*)Cbuf + (size_t)(row0 + mloc)*LDB + n0 + col;
                        float2 st; st.x = v0; st.y = v1;
                        *reinterpret_cast<float2*>(outp) = st;
                    }
                }
            }
        }
    }
}

// ---------------- 5) weighted combine ----------------
__global__ void combine_kernel(float* __restrict__ out){
    int i = blockIdx.x, t = threadIdx.x;
    int s0 = g_slot[i*2], s1 = g_slot[i*2+1];
    float w0 = g_wn[i*2], w1 = g_wn[i*2+1];
    const float4* y0 = reinterpret_cast<const float4*>(g_Y + (size_t)s0*HDIM);
    const float4* y1 = reinterpret_cast<const float4*>(g_Y + (size_t)s1*HDIM);
    float4 a = y0[t], b = y1[t];
    float4 r;
    r.x = w0*a.x + w1*b.x; r.y = w0*a.y + w1*b.y;
    r.z = w0*a.z + w1*b.z; r.w = w0*a.w + w1*b.w;
    reinterpret_cast<float4*>(out + (size_t)i*HDIM)[t] = r;
}

// ---------------- launch ----------------
extern "C" void kernel_launch(void* const* d_in, const int* in_sizes, int n_in,
                              void* d_out, int out_size){
    const float* x       = (const float*)d_in[0];
    const int*   mapping = (const int*)  d_in[1];
    const float* Wg      = (const float*)d_in[2];
    const float* W1      = (const float*)d_in[3];
    const float* b1      = (const float*)d_in[4];
    const float* W2      = (const float*)d_in[5];
    const float* b2      = (const float*)d_in[6];
    float* out = (float*)d_out;

    float *pLog, *pSoft, *pY; __half *pXh, *pHh, *pW1h, *pW2h; int *pTok;
    cudaGetSymbolAddress((void**)&pLog,  g_logits);
    cudaGetSymbolAddress((void**)&pSoft, g_soft);
    cudaGetSymbolAddress((void**)&pXh,   g_xh);
    cudaGetSymbolAddress((void**)&pHh,   g_Hh);
    cudaGetSymbolAddress((void**)&pY,    g_Y);
    cudaGetSymbolAddress((void**)&pW1h,  g_W1h);
    cudaGetSymbolAddress((void**)&pW2h,  g_W2h);
    cudaGetSymbolAddress((void**)&pTok,  g_pairtok);

    convw_kernel<<<2048, 256>>>(W1, W2, pW1h, pW2h);
    gate_kernel<<<N_TOK, 256>>>(x, Wg, pLog, pXh);
    colsoftmax_kernel<<<NEXP, 256>>>(pLog, pSoft);
    assign_kernel<<<1, 512>>>(mapping, pSoft);

    cudaFuncSetAttribute(moe_gemm_fp16<HDIM, FDIM, true,  true >,
                         cudaFuncAttributeMaxDynamicSharedMemorySize, SMEM_BYTES);
    cudaFuncSetAttribute(moe_gemm_fp16<FDIM, HDIM, false, false>,
                         cudaFuncAttributeMaxDynamicSharedMemorySize, SMEM_BYTES);

    moe_gemm_fp16<HDIM, FDIM, true,  true ><<<dim3(MAXTILES, FDIM/BN), 512, SMEM_BYTES>>>(pXh, pW1h, b1, pHh, pTok);
    moe_gemm_fp16<FDIM, HDIM, false, false><<<dim3(MAXTILES, HDIM/BN), 512, SMEM_BYTES>>>(pHh, pW2h, b2, pY,  pTok);

    combine_kernel<<<N_TOK, 256>>>(out);
}

// round 11
// speedup vs baseline: 1.8804x; 1.1863x over previous
#include <cuda_runtime.h>
#include <cuda_fp16.h>
#include <math.h>
#include <cstdint>

#define N_TOK 2048
#define HDIM 1024
#define FDIM 4096
#define NEXP 8
#define KSEL 2
#define NPAIR (N_TOK*KSEL)
#define MAXTILES 40
#define BK 32
#define BN 256

// ---------------- scratch (static device globals) ----------------
__device__ float  g_logits[N_TOK*NEXP];
__device__ float  g_soft[N_TOK*NEXP];
__device__ float  g_wn[NPAIR];
__device__ int    g_slot[NPAIR];
__device__ int    g_pairtok[NPAIR];
__device__ int    g_tiles[MAXTILES*3];
__device__ int    g_ntiles;
__device__ __half g_xh[(size_t)N_TOK*HDIM];
__device__ __half g_Hh[(size_t)(NPAIR+128)*FDIM];
__device__ float  g_Y[(size_t)(NPAIR+128)*HDIM];
__device__ __half g_W1h[(size_t)NEXP*HDIM*FDIM];
__device__ __half g_W2h[(size_t)NEXP*FDIM*HDIM];

// ---------------- helpers ----------------
__device__ __forceinline__ uint32_t pack_h2(float lo, float hi){
    uint32_t r;
    asm("cvt.rn.f16x2.f32 %0, %1, %2;" : "=r"(r) : "f"(hi), "f"(lo));
    return r;
}

__device__ __forceinline__ uint32_t smem_u32(const void* p){
    uint32_t a;
    asm("{ .reg .u64 t; cvta.to.shared.u64 t, %1; cvt.u32.u64 %0, t; }" : "=r"(a) : "l"(p));
    return a;
}

#define CP_ASYNC16(dst, src) \
    asm volatile("cp.async.cg.shared.global [%0], [%1], 16;" :: "r"(dst), "l"(src) : "memory")
#define CP_COMMIT() asm volatile("cp.async.commit_group;" ::: "memory")
#define CP_WAIT1()  asm volatile("cp.async.wait_group 1;" ::: "memory")

__device__ __forceinline__ void ldsm_x4(uint32_t& r0, uint32_t& r1, uint32_t& r2, uint32_t& r3,
                                        uint32_t addr){
    asm volatile("ldmatrix.sync.aligned.m8n8.x4.shared.b16 {%0,%1,%2,%3}, [%4];"
        : "=r"(r0), "=r"(r1), "=r"(r2), "=r"(r3) : "r"(addr));
}
__device__ __forceinline__ void ldsm_x4_t(uint32_t& r0, uint32_t& r1, uint32_t& r2, uint32_t& r3,
                                          uint32_t addr){
    asm volatile("ldmatrix.sync.aligned.m8n8.x4.trans.shared.b16 {%0,%1,%2,%3}, [%4];"
        : "=r"(r0), "=r"(r1), "=r"(r2), "=r"(r3) : "r"(addr));
}

__device__ __forceinline__ void mma_fp16(float c[4], uint32_t a0, uint32_t a1, uint32_t a2, uint32_t a3,
                                         uint32_t b0, uint32_t b1){
    asm volatile("mma.sync.aligned.m16n8k16.row.col.f32.f16.f16.f32 "
        "{%0,%1,%2,%3}, {%4,%5,%6,%7}, {%8,%9}, {%0,%1,%2,%3};\n"
        : "+f"(c[0]),"+f"(c[1]),"+f"(c[2]),"+f"(c[3])
        : "r"(a0),"r"(a1),"r"(a2),"r"(a3),"r"(b0),"r"(b1));
}

__device__ __forceinline__ float gelu_t(float v){
    float u = 0.7978845608028654f*(v + 0.044715f*v*v*v);
    return 0.5f*v*(1.f + tanhf(u));
}

// ---------------- 1) merged: gate (blocks 0..N_TOK-1) + weight conversion (blocks N_TOK..) ----------------
__global__ void prep_kernel(const float* __restrict__ x, const float* __restrict__ Wg,
                            const float* __restrict__ W1, const float* __restrict__ W2,
                            float* __restrict__ logits, __half* __restrict__ xh,
                            __half* __restrict__ W1h, __half* __restrict__ W2h){
    if (blockIdx.x < N_TOK){
        int i = blockIdx.x;
        int wid = threadIdx.x >> 5;
        int lane = threadIdx.x & 31;
        const float4* x4 = reinterpret_cast<const float4*>(x + (size_t)i*HDIM);
        const float4* w4 = reinterpret_cast<const float4*>(Wg + (size_t)wid*HDIM);
        float s = 0.f;
        #pragma unroll
        for (int k = lane; k < HDIM/4; k += 32){
            float4 a = x4[k], b = w4[k];
            s += a.x*b.x + a.y*b.y + a.z*b.z + a.w*b.w;
            if (wid == 0){
                uint2 h; h.x = pack_h2(a.x, a.y); h.y = pack_h2(a.z, a.w);
                *reinterpret_cast<uint2*>(xh + (size_t)i*HDIM + k*4) = h;
            }
        }
        #pragma unroll
        for (int o = 16; o; o >>= 1) s += __shfl_xor_sync(0xffffffffu, s, o);
        if (lane == 0) logits[i*NEXP + wid] = s;
    } else {
        size_t n4 = (size_t)NEXP*HDIM*FDIM/4;
        size_t stride = (size_t)2048*blockDim.x;
        for (size_t i = (size_t)(blockIdx.x - N_TOK)*blockDim.x + threadIdx.x; i < n4; i += stride){
            float4 v = reinterpret_cast<const float4*>(W1)[i];
            uint2 h; h.x = pack_h2(v.x, v.y); h.y = pack_h2(v.z, v.w);
            reinterpret_cast<uint2*>(W1h)[i] = h;
            float4 w = reinterpret_cast<const float4*>(W2)[i];
            uint2 g; g.x = pack_h2(w.x, w.y); g.y = pack_h2(w.z, w.w);
            reinterpret_cast<uint2*>(W2h)[i] = g;
        }
    }
}

// ---------------- 2) softmax over axis=0 ----------------
__global__ void colsoftmax_kernel(const float* __restrict__ logits, float* __restrict__ soft){
    int e = blockIdx.x;
    int t = threadIdx.x;
    __shared__ float red[256];
    float m = -1e30f;
    for (int i = t; i < N_TOK; i += 256) m = fmaxf(m, logits[i*NEXP + e]);
    red[t] = m; __syncthreads();
    for (int o = 128; o; o >>= 1){ if (t < o) red[t] = fmaxf(red[t], red[t+o]); __syncthreads(); }
    float mx = red[0]; __syncthreads();
    float sum = 0.f;
    for (int i = t; i < N_TOK; i += 256) sum += expf(logits[i*NEXP + e] - mx);
    red[t] = sum; __syncthreads();
    for (int o = 128; o; o >>= 1){ if (t < o) red[t] += red[t+o]; __syncthreads(); }
    float inv = 1.f / red[0];
    for (int i = t; i < N_TOK; i += 256)
        soft[i*NEXP + e] = expf(logits[i*NEXP + e] - mx) * inv;
}

// ---------------- 3) assignment via shared atomics ----------------
// Slot order within an expert is atomics-order dependent, but the final output is
// bitwise invariant to that permutation (each slot's row depends only on its own
// (token, expert); combine reads back through g_slot).
__global__ void assign_kernel(const int* __restrict__ mapping, const float* __restrict__ soft){
    __shared__ int cnt[NEXP];
    __shared__ int pos[NEXP];
    int t = threadIdx.x;    // 512
    if (t < NEXP) cnt[t] = 0;
    __syncthreads();
    for (int p = t; p < NPAIR; p += 512)
        atomicAdd(&cnt[mapping[p]], 1);
    __syncthreads();
    if (t == 0){
        int acc = 0, nt = 0;
        for (int e = 0; e < NEXP; e++){
            pos[e] = acc;
            int c = cnt[e];
            for (int r = 0; r < c; r += 128){
                g_tiles[nt*3+0] = e;
                g_tiles[nt*3+1] = acc + r;
                g_tiles[nt*3+2] = min(128, c - r);
                nt++;
            }
            acc += c;
        }
        g_ntiles = nt;
    }
    __syncthreads();
    for (int p = t; p < NPAIR; p += 512){
        int e = mapping[p];
        int d = atomicAdd(&pos[e], 1);
        g_slot[p] = d;
        g_pairtok[d] = p >> 1;
    }
    for (int i = t; i < N_TOK; i += 512){
        int e0 = mapping[i*KSEL], e1 = mapping[i*KSEL+1];
        float w0 = soft[i*NEXP + e0], w1 = soft[i*NEXP + e1];
        float inv = 1.f / (w0 + w1);
        g_wn[i*KSEL]   = w0*inv;
        g_wn[i*KSEL+1] = w1*inv;
    }
}

// ---------------- 4) fp16 grouped GEMM: 128x256 tile, BK=32, 16 warps, 32x64 warp tile ----------------
// 3-stage cp.async pipeline. A smem: [3][128][40] half. B smem: [3][32][264] half.
#define ASTR 40
#define BSTR 264
#define ASZ (128*ASTR)
#define BSZ (BK*BSTR)
#define NSTAGE 3
#define SMEM_BYTES (NSTAGE*(ASZ + BSZ) * 2)

template<int KSIZE, int LDB, bool GELU, bool GATHER>
__global__ __launch_bounds__(512, 1) void moe_gemm_fp16(
    const __half* __restrict__ Asrc,
    const __half* __restrict__ Ball,
    const float* __restrict__ bias,
    void* __restrict__ Cbuf,
    const int* __restrict__ pairtok)
{
    int tileIdx = blockIdx.x;
    if (tileIdx >= g_ntiles) return;
    int e    = g_tiles[tileIdx*3+0];
    int row0 = g_tiles[tileIdx*3+1];
    int rows = g_tiles[tileIdx*3+2];
    int n0   = blockIdx.y * BN;

    extern __shared__ __half smem[];
    __half* As = smem;                    // [3][128][ASTR]
    __half* Bs = smem + NSTAGE*ASZ;       // [3][BK][BSTR]

    int tid = threadIdx.x;
    int wid = tid >> 5, lane = tid & 31;
    int wm = (wid >> 2) * 32, wn = (wid & 3) * 64;

    // ---- A staging ----
    int arow = tid >> 2;
    int koff = (tid & 3) * 8;
    const __half* aH;
    if (GATHER){
        int rr = row0 + ((arow < rows) ? arow : (rows - 1));
        aH = Asrc + (size_t)pairtok[rr] * KSIZE + koff;
    } else {
        aH = Asrc + (size_t)(row0 + arow) * KSIZE + koff;
    }
    uint32_t sbA = smem_u32(As);
    uint32_t sbB = smem_u32(Bs);
    uint32_t a_dst0 = sbA + (uint32_t)(arow*ASTR + koff)*2u;

    // ---- B staging ----
    int brow = tid >> 4;
    int bcol = (tid & 15) * 16;
    const __half* bp0 = Ball + (size_t)e * KSIZE * LDB + (size_t)brow * LDB + n0 + bcol;
    uint32_t b_dst0 = sbB + (uint32_t)(brow*BSTR + bcol)*2u;

    float c[2][8][4];
    #pragma unroll
    for (int i = 0; i < 2; i++)
        #pragma unroll
        for (int j = 0; j < 8; j++)
            #pragma unroll
            for (int q = 0; q < 4; q++) c[i][j][q] = 0.f;

    auto cp_tiles = [&](int buf, int kb){
        uint32_t da = a_dst0 + (uint32_t)buf*(ASZ*2);
        CP_ASYNC16(da, aH + kb*BK);
        uint32_t db = b_dst0 + (uint32_t)buf*(BSZ*2);
        const __half* bs = bp0 + (size_t)kb*BK*LDB;
        CP_ASYNC16(db,      bs);
        CP_ASYNC16(db + 16, bs + 8);
    };

    const int NKB = KSIZE / BK;
    cp_tiles(0, 0); CP_COMMIT();
    cp_tiles(1, 1); CP_COMMIT();

    // ---- per-lane ldmatrix address offsets ----
    int a_row = ((lane>>3)&1)*8 + (lane&7);
    int a_kof = ((lane>>4)&1)*8;
    int b_kr  = ((lane>>3)&1)*8 + (lane&7);
    int b_nof = ((lane>>4)&1)*8;

    uint32_t aoff = (uint32_t)((wm + a_row)*ASTR + a_kof) * 2u;
    uint32_t boff = (uint32_t)(b_kr*BSTR + wn + b_nof) * 2u;

    int cur = 0, nxt = 2;   // nxt = (kb+2) % NSTAGE
    for (int kb = 0; kb < NKB; kb++){
        CP_WAIT1();          // stage kb's group complete (exactly 1 newer group pending)
        __syncthreads();
        if (kb + 2 < NKB) cp_tiles(nxt, kb + 2);
        CP_COMMIT();         // unconditional: keeps group accounting exact through the tail

        uint32_t abase = sbA + (uint32_t)cur*(ASZ*2) + aoff;
        uint32_t bbase = sbB + (uint32_t)cur*(BSZ*2) + boff;
        #pragma unroll
        for (int ks = 0; ks < 2; ks++){
            uint32_t afr[2][4], bfr[8][2];
            #pragma unroll
            for (int fm = 0; fm < 2; fm++)
                ldsm_x4(afr[fm][0], afr[fm][1], afr[fm][2], afr[fm][3],
                        abase + (uint32_t)(fm*16*ASTR*2) + (uint32_t)(ks*32));
            #pragma unroll
            for (int fn2 = 0; fn2 < 4; fn2++)
                ldsm_x4_t(bfr[2*fn2][0], bfr[2*fn2][1], bfr[2*fn2+1][0], bfr[2*fn2+1][1],
                          bbase + (uint32_t)(ks*16*BSTR*2) + (uint32_t)(fn2*32));
            #pragma unroll
            for (int fm = 0; fm < 2; fm++)
                #pragma unroll
                for (int fn = 0; fn < 8; fn++)
                    mma_fp16(c[fm][fn], afr[fm][0], afr[fm][1], afr[fm][2], afr[fm][3],
                             bfr[fn][0], bfr[fn][1]);
        }
        cur = (cur == NSTAGE-1) ? 0 : cur + 1;
        nxt = (nxt == NSTAGE-1) ? 0 : nxt + 1;
    }

    // ---- epilogue ----
    int r_lane = lane >> 2, c_lane = (lane & 3) * 2;
    #pragma unroll
    for (int fm = 0; fm < 2; fm++){
        #pragma unroll
        for (int half_i = 0; half_i < 2; half_i++){
            int mloc = wm + fm*16 + half_i*8 + r_lane;
            if (mloc < rows){
                const float* brw = bias + (size_t)e*LDB + n0;
                #pragma unroll
                for (int fn = 0; fn < 8; fn++){
                    int col = wn + fn*8 + c_lane;
                    float v0 = c[fm][fn][half_i*2+0] + brw[col];
                    float v1 = c[fm][fn][half_i*2+1] + brw[col+1];
                    if (GELU){
                        v0 = gelu_t(v0); v1 = gelu_t(v1);
                        __half* outp = (__half*)Cbuf + (size_t)(row0 + mloc)*LDB + n0 + col;
                        *reinterpret_cast<uint32_t*>(outp) = pack_h2(v0, v1);
                    } else {
                        float* outp = (float*)Cbuf + (size_t)(row0 + mloc)*LDB + n0 + col;
                        float2 st; st.x = v0; st.y = v1;
                        *reinterpret_cast<float2*>(outp) = st;
                    }
                }
            }
        }
    }
}

// ---------------- 5) weighted combine ----------------
__global__ void combine_kernel(float* __restrict__ out){
    int i = blockIdx.x, t = threadIdx.x;
    int s0 = g_slot[i*2], s1 = g_slot[i*2+1];
    float w0 = g_wn[i*2], w1 = g_wn[i*2+1];
    const float4* y0 = reinterpret_cast<const float4*>(g_Y + (size_t)s0*HDIM);
    const float4* y1 = reinterpret_cast<const float4*>(g_Y + (size_t)s1*HDIM);
    float4 a = y0[t], b = y1[t];
    float4 r;
    r.x = w0*a.x + w1*b.x; r.y = w0*a.y + w1*b.y;
    r.z = w0*a.z + w1*b.z; r.w = w0*a.w + w1*b.w;
    reinterpret_cast<float4*>(out + (size_t)i*HDIM)[t] = r;
}

// ---------------- launch ----------------
extern "C" void kernel_launch(void* const* d_in, const int* in_sizes, int n_in,
                              void* d_out, int out_size){
    const float* x       = (const float*)d_in[0];
    const int*   mapping = (const int*)  d_in[1];
    const float* Wg      = (const float*)d_in[2];
    const float* W1      = (const float*)d_in[3];
    const float* b1      = (const float*)d_in[4];
    const float* W2      = (const float*)d_in[5];
    const float* b2      = (const float*)d_in[6];
    float* out = (float*)d_out;

    float *pLog, *pSoft, *pY; __half *pXh, *pHh, *pW1h, *pW2h; int *pTok;
    cudaGetSymbolAddress((void**)&pLog,  g_logits);
    cudaGetSymbolAddress((void**)&pSoft, g_soft);
    cudaGetSymbolAddress((void**)&pXh,   g_xh);
    cudaGetSymbolAddress((void**)&pHh,   g_Hh);
    cudaGetSymbolAddress((void**)&pY,    g_Y);
    cudaGetSymbolAddress((void**)&pW1h,  g_W1h);
    cudaGetSymbolAddress((void**)&pW2h,  g_W2h);
    cudaGetSymbolAddress((void**)&pTok,  g_pairtok);

    prep_kernel<<<N_TOK + 2048, 256>>>(x, Wg, W1, W2, pLog, pXh, pW1h, pW2h);
    colsoftmax_kernel<<<NEXP, 256>>>(pLog, pSoft);
    assign_kernel<<<1, 512>>>(mapping, pSoft);

    cudaFuncSetAttribute(moe_gemm_fp16<HDIM, FDIM, true,  true >,
                         cudaFuncAttributeMaxDynamicSharedMemorySize, SMEM_BYTES);
    cudaFuncSetAttribute(moe_gemm_fp16<FDIM, HDIM, false, false>,
                         cudaFuncAttributeMaxDynamicSharedMemorySize, SMEM_BYTES);

    moe_gemm_fp16<HDIM, FDIM, true,  true ><<<dim3(MAXTILES, FDIM/BN), 512, SMEM_BYTES>>>(pXh, pW1h, b1, pHh, pTok);
    moe_gemm_fp16<FDIM, HDIM, false, false><<<dim3(MAXTILES, HDIM/BN), 512, SMEM_BYTES>>>(pHh, pW2h, b2, pY,  pTok);

    combine_kernel<<<N_TOK, 256>>>(out);
}